// round 17
// baseline (speedup 1.0000x reference)
#include <cuda_runtime.h>

// Problem constants (fixed by reference)
#define NTIME 128
#define NBATCH 1024
#define NSAMP (NTIME*NBATCH)   // 131072
#define NSIZE 8
#define HID 64
#define IN_DIM 10
#define NC 12                  // 1 value col + 10 tangent cols + 1 zero pad
#define BS 32                  // samples per tile
#define NCOL (BS*NC)           // 384
#define NT 512                 // see phase mappings
#define NTILES (NSAMP / BS)    // 4096 (exact)
#define GRID 148

typedef unsigned long long u64;

struct SM {
  float A[HID*NCOL];        // 98304 B — single in-place state buffer
  float S8[NSIZE*NCOL];     // 12288 B — end-layer output
  float w1t[HID*HID];       // w_int[0] transposed: [k][i]
  float w2t[HID*HID];       // w_int[1] transposed
  float wedt[HID*2*NSIZE];  // w_end k-major + duplicated: [k][2r],[2r+1]
  float ws[HID*IN_DIM];     // w_start row-major
  float bs[HID];
  float b1[HID];
  float b2[HID];
  float be[NSIZE];
  float pconst, Econst;
};

__device__ __forceinline__ u64 pack2(float a, float b) {
  u64 r; asm("mov.b64 %0, {%1, %2};" : "=l"(r) : "f"(a), "f"(b)); return r;
}
__device__ __forceinline__ void unpack2(u64 v, float& a, float& b) {
  asm("mov.b64 {%0, %1}, %2;" : "=f"(a), "=f"(b) : "l"(v));
}
__device__ __forceinline__ void fma2(u64& d, u64 a, u64 b) {
  asm("fma.rn.f32x2 %0, %1, %2, %3;" : "=l"(d) : "l"(a), "l"(b), "l"(d));
}

// Whole-sample hidden-layer k-loop. Thread (ty=warp, samp=lane): rows
// r0..r0+7, ALL 12 columns of sample samp (col 11 = pad stays 0; col 10
// kept as a scalar fmaf chain so the pad pair is never materialized).
// acc[cp][r] covers cols {2cp, 2cp+1}; bias pre-loaded into col 0 (lo lane).
// k-summation strictly sequential 0..63 per output (exact numerics).
__device__ __forceinline__ void kloop64(const float* __restrict__ Wt,
                                        const float* __restrict__ bias,
                                        const float* __restrict__ X,
                                        u64 (&acc)[5][8], float (&acc10)[8],
                                        int r0, int samp)
{
  #pragma unroll
  for (int cp = 0; cp < 5; cp++)
    #pragma unroll
    for (int r = 0; r < 8; r++) acc[cp][r] = 0ull;
  #pragma unroll
  for (int r = 0; r < 8; r++) {
    acc[0][r] = pack2(bias[r0 + r], 0.f);
    acc10[r] = 0.f;
  }

  const float* Xb = X + samp*NC;
  const float* Wb = Wt + r0;

  #pragma unroll 2
  for (int k = 0; k < HID; k++) {
    const float* xrow = Xb + (size_t)k*NCOL;
    ulonglong2 x01 = *reinterpret_cast<const ulonglong2*>(xrow);      // cols 0..3
    ulonglong2 x23 = *reinterpret_cast<const ulonglong2*>(xrow + 4);  // cols 4..7
    u64 x4 = *reinterpret_cast<const u64*>(xrow + 8);                 // cols 8..9
    float x10 = xrow[10];
    u64 xp[5] = { x01.x, x01.y, x23.x, x23.y, x4 };

    float4 wa  = *reinterpret_cast<const float4*>(Wb + k*HID);
    float4 wb4 = *reinterpret_cast<const float4*>(Wb + k*HID + 4);
    float wf[8] = { wa.x, wa.y, wa.z, wa.w, wb4.x, wb4.y, wb4.z, wb4.w };
    u64 wd[8];
    #pragma unroll
    for (int r = 0; r < 8; r++) wd[r] = pack2(wf[r], wf[r]);

    #pragma unroll
    for (int cp = 0; cp < 5; cp++)
      #pragma unroll
      for (int r = 0; r < 8; r++)
        fma2(acc[cp][r], wd[r], xp[cp]);
    #pragma unroll
    for (int r = 0; r < 8; r++)
      acc10[r] = fmaf(wf[r], x10, acc10[r]);
  }
}

// Masked in-place store of one layer's outputs (pre = col0, bias included).
__device__ __forceinline__ void store_masked(float* __restrict__ X,
                                             u64 (&acc)[5][8],
                                             float (&acc10)[8],
                                             int r0, int samp)
{
  #pragma unroll
  for (int r = 0; r < 8; r++) {
    float v[12];
    #pragma unroll
    for (int cp = 0; cp < 5; cp++) unpack2(acc[cp][r], v[2*cp], v[2*cp + 1]);
    v[10] = acc10[r];
    float pre = v[0];
    float m = pre > 0.f ? 1.f : 0.f;
    v[0] = pre > 0.f ? pre : 0.f;
    #pragma unroll
    for (int j = 1; j < 11; j++) v[j] *= m;
    float* rp = X + (r0 + r)*NCOL + samp*NC;
    reinterpret_cast<float4*>(rp)[0] = make_float4(v[0], v[1], v[2],  v[3]);
    reinterpret_cast<float4*>(rp)[1] = make_float4(v[4], v[5], v[6],  v[7]);
    reinterpret_cast<float4*>(rp)[2] = make_float4(v[8], v[9], v[10], 0.f);
  }
}

__global__ __launch_bounds__(NT) void model_kernel(
    const float* __restrict__ y, const float* __restrict__ erate,
    const float* __restrict__ Tp, const float* __restrict__ Ep,
    const float* __restrict__ np_, const float* __restrict__ w_start,
    const float* __restrict__ b_start, const float* __restrict__ w_int,
    const float* __restrict__ b_int, const float* __restrict__ w_end,
    const float* __restrict__ b_end, float* __restrict__ out)
{
  extern __shared__ char smraw[];
  SM& s = *reinterpret_cast<SM*>(smraw);
  const int tid = threadIdx.x;

  // ---- one-time weight load: transpose hidden; w_end -> k-major duplicated ----
  for (int idx = tid; idx < HID*HID; idx += NT) {
    int i = idx / HID, k = idx % HID;
    s.w1t[k*HID + i] = w_int[idx];
    s.w2t[k*HID + i] = w_int[HID*HID + idx];
  }
  for (int idx = tid; idx < NSIZE*HID; idx += NT) {
    int r = idx / HID, k = idx % HID;
    float v = w_end[idx];
    s.wedt[k*2*NSIZE + 2*r]     = v;
    s.wedt[k*2*NSIZE + 2*r + 1] = v;
  }
  for (int idx = tid; idx < HID*IN_DIM; idx += NT) s.ws[idx] = w_start[idx];
  if (tid < HID) { s.bs[tid] = b_start[tid]; s.b1[tid] = b_int[tid]; s.b2[tid] = b_int[HID + tid]; }
  else if (tid < HID + NSIZE) s.be[tid - HID] = b_end[tid - HID];
  else if (tid == HID + NSIZE) { s.pconst = expf(np_[0]); s.Econst = expf(Ep[0]); }
  __syncthreads();   // fence weight/bias/const writes before any tile reads

  // hidden-layer mapping: warp = ty (rows warp*8..+7), lane = sample. 256 thr.
  const int warp = tid >> 5;
  const int lane = tid & 31;
  const int r0   = warp * 8;

  // start-layer mapping (all 512 threads: 16 row-groups x 32 samples)
  const int sty = tid / 32;
  const int stx = tid % 32;
  const int sr0 = sty * 4;
  const int sc0 = stx * NC;

  u64 acc[5][8];
  float acc10[8];

  for (int tile = blockIdx.x; tile < NTILES; tile += GRID) {
    const int samp0 = tile * BS;

    // ---- start layer straight from GLOBAL inputs (all 512 threads) ----
    // col0 = relu(Ws x + b); tangent col j = mask*Ws[:,j]; pad=0
    {
      const int gg = samp0 + stx;
      float xin[IN_DIM];
      #pragma unroll
      for (int j = 0; j < NSIZE; j++) xin[j] = y[(size_t)gg*NSIZE + j];
      xin[8] = erate[gg];
      xin[9] = Tp[gg];
      #pragma unroll
      for (int r = 0; r < 4; r++) {
        int i = sr0 + r;
        float wrow[IN_DIM];
        #pragma unroll
        for (int j = 0; j < IN_DIM; j++) wrow[j] = s.ws[i*IN_DIM + j];
        float pre = s.bs[i];
        #pragma unroll
        for (int j = 0; j < IN_DIM; j++) pre = fmaf(wrow[j], xin[j], pre);
        float m = pre > 0.f ? 1.f : 0.f;
        float v0 = pre > 0.f ? pre : 0.f;
        float4* ar = reinterpret_cast<float4*>(s.A + i*NCOL + sc0);
        ar[0] = make_float4(v0, m*wrow[0], m*wrow[1], m*wrow[2]);
        ar[1] = make_float4(m*wrow[3], m*wrow[4], m*wrow[5], m*wrow[6]);
        ar[2] = make_float4(m*wrow[7], m*wrow[8], m*wrow[9], 0.f);
      }
    }
    __syncthreads();                                    // bar 1

    // ---- hidden layer 1 (threads 0..255) ----
    if (tid < 256) kloop64(s.w1t, s.b1, s.A, acc, acc10, r0, lane);
    __syncthreads();                                    // bar 2 (X reads done)
    if (tid < 256) store_masked(s.A, acc, acc10, r0, lane);
    __syncthreads();                                    // bar 3

    // ---- hidden layer 2 (threads 0..255) ----
    if (tid < 256) kloop64(s.w2t, s.b2, s.A, acc, acc10, r0, lane);
    __syncthreads();                                    // bar 4
    if (tid < 256) store_masked(s.A, acc, acc10, r0, lane);
    __syncthreads();                                    // bar 5

    // ---- end layer on threads 0..383: rows as quads (R=4), col-pairs ----
    // k strictly sequential 0..63 per output, bias after loop (exact numerics).
    if (tid < 384) {
      const int ecp = tid >> 1;       // col-pair 0..191
      const int erq = tid & 1;        // row-quad 0..1
      const int c = 2*ecp;
      u64 acc0 = 0ull, acc1 = 0ull, acc2 = 0ull, acc3 = 0ull;
      const float* xb = s.A + c;
      const float* wt = s.wedt + 8*erq;
      #pragma unroll 8
      for (int k = 0; k < HID; k++) {
        u64 xv = *reinterpret_cast<const u64*>(xb + k*NCOL);
        ulonglong2 w01 = *reinterpret_cast<const ulonglong2*>(wt + k*2*NSIZE);
        ulonglong2 w23 = *reinterpret_cast<const ulonglong2*>(wt + k*2*NSIZE + 4);
        fma2(acc0, w01.x, xv);
        fma2(acc1, w01.y, xv);
        fma2(acc2, w23.x, xv);
        fma2(acc3, w23.y, xv);
      }
      const int rb = 4*erq;
      float lo, hi;
      unpack2(acc0, lo, hi);
      if ((c % NC) == 0) lo += s.be[rb];
      *reinterpret_cast<float2*>(s.S8 + (rb    )*NCOL + c) = make_float2(lo, hi);
      unpack2(acc1, lo, hi);
      if ((c % NC) == 0) lo += s.be[rb + 1];
      *reinterpret_cast<float2*>(s.S8 + (rb + 1)*NCOL + c) = make_float2(lo, hi);
      unpack2(acc2, lo, hi);
      if ((c % NC) == 0) lo += s.be[rb + 2];
      *reinterpret_cast<float2*>(s.S8 + (rb + 2)*NCOL + c) = make_float2(lo, hi);
      unpack2(acc3, lo, hi);
      if ((c % NC) == 0) lo += s.be[rb + 3];
      *reinterpret_cast<float2*>(s.S8 + (rb + 3)*NCOL + c) = make_float2(lo, hi);
    }
    __syncthreads();                                    // bar 6

    // ---- outputs on threads 384..511 (x2 iterations): overlap with next
    // tile's start layer. Safety: S8 reads finish before these threads join
    // bar 1 of tile t+1; S8 is next written only after bar 5 of t+1.
    if (tid >= 384) {
      #pragma unroll
      for (int it = 0; it < 2; it++) {
        int o = (tid - 384) + it*128;   // 0..255
        int sm = o >> 3;
        int r  = o & 7;
        int gg = samp0 + sm;
        int cc = sm * NC;

        const float4* s4 = reinterpret_cast<const float4*>(s.S8 + r*NCOL + cc);
        float4 Sa = s4[0], Sb = s4[1], Sc = s4[2];
        float S[11] = { Sa.x, Sa.y, Sa.z, Sa.w, Sb.x, Sb.y, Sb.z, Sb.w,
                        Sc.x, Sc.y, Sc.z };

        float st0 = s.S8[cc];               // row-0 value col (broadcast)
        float y0  = y[(size_t)gg*NSIZE];
        float sg  = (y0 > 0.f) ? 1.f : ((y0 < 0.f) ? -1.f : 0.f);
        float a   = fabsf(y0);
        float p   = s.pconst;
        float Ee  = s.Econst;
        float onep = 1.f + st0 * 1e-5f;
        float u   = a * onep;
        float gv  = (u > 0.f) ? powf(u, p) : 0.f;   // macaulay(g)=g since g>=0
        float dgdu = (u > 0.f) ? p * gv / u : 0.f;
        float coef = -Ee * sg * dgdu;
        float son  = sg * onep;
        float a5   = a * 1e-5f;

        float rate, j1[8], j2v, j3v;
        if (r == 0) {
          float er = erate[gg];
          rate = Ee * (er - gv * sg);
          #pragma unroll
          for (int j = 0; j < 8; j++) {
            float du = a5 * S[1 + j] + (j == 0 ? son : 0.f);
            j1[j] = coef * du;
          }
          j2v = Ee + coef * (a5 * S[9]);
          j3v = coef * (a5 * S[10]);
        } else {
          rate = S[0] * 1e-4f;
          #pragma unroll
          for (int j = 0; j < 8; j++) j1[j] = S[1 + j] * 1e-4f;
          j2v = S[9]  * 1e-4f;
          j3v = S[10] * 1e-4f;
        }

        out[(size_t)gg*NSIZE + r] = rate;
        const size_t b1o = (size_t)NSAMP * NSIZE;
        float* o1 = out + b1o + (size_t)gg*64 + (size_t)r*8;
        #pragma unroll
        for (int j = 0; j < 8; j++) o1[j] = j1[j];
        const size_t b2o = b1o + (size_t)NSAMP * 64;
        out[b2o + (size_t)gg*NSIZE + r] = j2v;
        out[b2o + (size_t)NSAMP*NSIZE + (size_t)gg*NSIZE + r] = j3v;
      }
    }
    // no trailing barrier (A-write vs end-layer-read fenced by bar 6)
  }
}

extern "C" void kernel_launch(void* const* d_in, const int* in_sizes, int n_in,
                              void* d_out, int out_size)
{
  const float* y       = (const float*)d_in[1];
  const float* erate   = (const float*)d_in[2];
  const float* T       = (const float*)d_in[3];
  const float* E       = (const float*)d_in[4];
  const float* n       = (const float*)d_in[5];
  const float* w_start = (const float*)d_in[6];
  const float* b_start = (const float*)d_in[7];
  const float* w_int   = (const float*)d_in[8];
  const float* b_int   = (const float*)d_in[9];
  const float* w_end   = (const float*)d_in[10];
  const float* b_end   = (const float*)d_in[11];
  float* out = (float*)d_out;

  int shbytes = (int)sizeof(SM);
  cudaFuncSetAttribute(model_kernel, cudaFuncAttributeMaxDynamicSharedMemorySize, shbytes);
  model_kernel<<<GRID, NT, shbytes>>>(y, erate, T, E, n, w_start, b_start,
                                      w_int, b_int, w_end, b_end, out);
}